// round 1
// baseline (speedup 1.0000x reference)
#include <cuda_runtime.h>

// Problem constants (fixed-shape benchmark)
#define FEAT 256
#define EMB  256
#define NSAMP 32
#define BATCH 10000

// Scratch (no device allocation allowed -> __device__ globals)
__device__ float g_M[FEAT * FEAT];     // Wq @ Wk^T
__device__ float g_u0[FEAT];           // Wk @ bq
__device__ float g_U[BATCH * FEAT];    // per-batch score vector in feature space
__device__ float g_agg[BATCH * FEAT];  // attention-weighted neighbor features

// ---------------------------------------------------------------------------
// Tiled SGEMM: C[M,N] = A[M,K] @ B[K,N] (+ bias[N])
//   TRANSB: B_logical[k][n] = Bp[n*K + k]   (for Wq @ Wk^T)
//   HASIDX: A row m is gathered as A[idx[m]] (for id2feat[nodes])
// BM=64, BN=64, BK=16, 256 threads, 4x4 register tile per thread.
// ---------------------------------------------------------------------------
template <bool TRANSB, bool HASIDX>
__global__ void sgemm64(const float* __restrict__ A, const float* __restrict__ Bp,
                        float* __restrict__ C, const float* __restrict__ bias,
                        const int* __restrict__ idx, int Mdim, int N, int K)
{
    constexpr int BM = 64, BN = 64, BK = 16;
    __shared__ float As[BK][BM];
    __shared__ float Bs[BK][BN];

    const int tid = threadIdx.x;
    const int tx = tid & 15;        // 0..15  -> 4 output cols each
    const int ty = tid >> 4;        // 0..15  -> 4 output rows each
    const int m0 = blockIdx.y * BM;
    const int n0 = blockIdx.x * BN;

    // A-tile load mapping: thread -> (row ar, k-quad akq)
    const int ar  = tid >> 2;       // 0..63
    const int akq = tid & 3;        // 0..3 (float4 along k)
    int mload = m0 + ar;
    if (mload > Mdim - 1) mload = Mdim - 1;
    const long arow = HASIDX ? (long)idx[mload] : (long)mload;
    const float4* Arow = (const float4*)(A + arow * (long)K);

    float acc[4][4] = {};

    for (int k0 = 0; k0 < K; k0 += BK) {
        // ---- load A tile (coalesced float4 along K), store transposed As[k][m]
        float4 av = Arow[(k0 >> 2) + akq];
        As[akq * 4 + 0][ar] = av.x;
        As[akq * 4 + 1][ar] = av.y;
        As[akq * 4 + 2][ar] = av.z;
        As[akq * 4 + 3][ar] = av.w;

        // ---- load B tile
        if (!TRANSB) {
            const int kr = tid >> 4;   // 0..15
            const int nq = tid & 15;   // 0..15
            float4 bv = *(const float4*)&Bp[(long)(k0 + kr) * N + n0 + nq * 4];
            ((float4*)Bs[kr])[nq] = bv;
        } else {
            const int bn  = tid >> 2;  // 0..63 (n within tile)
            const int kq2 = tid & 3;   // 0..3  (float4 along k)
            float4 bv = *(const float4*)&Bp[(long)(n0 + bn) * K + k0 + kq2 * 4];
            Bs[kq2 * 4 + 0][bn] = bv.x;
            Bs[kq2 * 4 + 1][bn] = bv.y;
            Bs[kq2 * 4 + 2][bn] = bv.z;
            Bs[kq2 * 4 + 3][bn] = bv.w;
        }
        __syncthreads();

        #pragma unroll
        for (int k = 0; k < BK; k++) {
            float4 a = *(const float4*)&As[k][ty * 4];
            float4 b = *(const float4*)&Bs[k][tx * 4];
            float av4[4] = {a.x, a.y, a.z, a.w};
            float bv4[4] = {b.x, b.y, b.z, b.w};
            #pragma unroll
            for (int i = 0; i < 4; i++)
                #pragma unroll
                for (int j = 0; j < 4; j++)
                    acc[i][j] += av4[i] * bv4[j];
        }
        __syncthreads();
    }

    // ---- epilogue (+bias), vectorized store
    float4 bvec = make_float4(0.f, 0.f, 0.f, 0.f);
    if (bias) bvec = *(const float4*)&bias[n0 + tx * 4];
    #pragma unroll
    for (int i = 0; i < 4; i++) {
        int m = m0 + ty * 4 + i;
        if (m < Mdim) {
            float4 o;
            o.x = acc[i][0] + bvec.x;
            o.y = acc[i][1] + bvec.y;
            o.z = acc[i][2] + bvec.z;
            o.w = acc[i][3] + bvec.w;
            *(float4*)&C[(long)m * N + n0 + tx * 4] = o;
        }
    }
}

// u0[f] = sum_e Wk[f][e] * bq[e]
__global__ void u0_kernel(const float* __restrict__ Wk, const float* __restrict__ bq,
                          float* __restrict__ u0)
{
    __shared__ float sb[EMB];
    const int t = threadIdx.x;
    sb[t] = bq[t];
    __syncthreads();
    float acc = 0.f;
    const float4* row = (const float4*)(Wk + (long)t * EMB);
    #pragma unroll 4
    for (int e4 = 0; e4 < EMB / 4; e4++) {
        float4 w = row[e4];
        acc += w.x * sb[e4 * 4 + 0] + w.y * sb[e4 * 4 + 1] +
               w.z * sb[e4 * 4 + 2] + w.w * sb[e4 * 4 + 3];
    }
    u0[t] = acc;
}

// ---------------------------------------------------------------------------
// Fused attention: one block per batch row.
//   score_s = x_s . U_b ; attn = softmax(score) ; agg_b = sum_s attn_s * x_s
// Neighbor rows staged in smem (single pass over the 327MB gather).
// ---------------------------------------------------------------------------
__global__ void attn_kernel(const float* __restrict__ id2feat,
                            const int* __restrict__ neigh_idx,
                            const float* __restrict__ U,
                            float* __restrict__ agg)
{
    __shared__ float sU[FEAT];
    __shared__ float sx[NSAMP][FEAT];
    __shared__ float sscore[NSAMP];

    const int b = blockIdx.x;
    const int tid = threadIdx.x;
    const int warp = tid >> 5, lane = tid & 31;

    sU[tid] = U[(long)b * FEAT + tid];
    __syncthreads();

    // Each of 8 warps handles 4 neighbors: gather row + dot with U in one pass.
    #pragma unroll
    for (int j = 0; j < 4; j++) {
        const int s = warp * 4 + j;
        const long row = neigh_idx[b * NSAMP + s];
        const float4* src = (const float4*)(id2feat + row * FEAT);
        const float4* su4 = (const float4*)sU;
        float dot = 0.f;
        #pragma unroll
        for (int i = 0; i < 2; i++) {
            const int q = lane + 32 * i;     // float4 index 0..63
            float4 v = src[q];
            ((float4*)sx[s])[q] = v;
            float4 u = su4[q];
            dot += v.x * u.x + v.y * u.y + v.z * u.z + v.w * u.w;
        }
        #pragma unroll
        for (int off = 16; off; off >>= 1)
            dot += __shfl_xor_sync(0xffffffffu, dot, off);
        if (lane == 0) sscore[s] = dot;
    }
    __syncthreads();

    // Softmax over 32 scores (warp 0); self column is masked in the reference,
    // so softmax over neighbors only.
    if (warp == 0) {
        float sc = sscore[lane];
        float mx = sc;
        #pragma unroll
        for (int off = 16; off; off >>= 1)
            mx = fmaxf(mx, __shfl_xor_sync(0xffffffffu, mx, off));
        float e = __expf(sc - mx);
        float sum = e;
        #pragma unroll
        for (int off = 16; off; off >>= 1)
            sum += __shfl_xor_sync(0xffffffffu, sum, off);
        sscore[lane] = e / sum;
    }
    __syncthreads();

    // Weighted sum: thread tid owns feature tid. sx[s][tid] is conflict-free.
    float acc = 0.f;
    #pragma unroll
    for (int s = 0; s < NSAMP; s++)
        acc += sscore[s] * sx[s][tid];
    agg[(long)b * FEAT + tid] = acc;
}

extern "C" void kernel_launch(void* const* d_in, const int* in_sizes, int n_in,
                              void* d_out, int out_size)
{
    const int*   nodes   = (const int*)d_in[0];
    const int*   neigh   = (const int*)d_in[1];
    const float* id2feat = (const float*)d_in[2];
    const float* Wq      = (const float*)d_in[3];
    const float* bq      = (const float*)d_in[4];
    const float* Wk      = (const float*)d_in[5];
    // d_in[6] = bk: score contribution Q.bk is constant across s -> softmax invariant, unused
    const float* Wv      = (const float*)d_in[7];
    const float* bv      = (const float*)d_in[8];
    float* out = (float*)d_out;

    float *pM, *pu0, *pU, *pagg;
    cudaGetSymbolAddress((void**)&pM,   g_M);
    cudaGetSymbolAddress((void**)&pu0,  g_u0);
    cudaGetSymbolAddress((void**)&pU,   g_U);
    cudaGetSymbolAddress((void**)&pagg, g_agg);

    // 1) M = Wq @ Wk^T  (tiny: 256x256x256)
    sgemm64<true, false><<<dim3(FEAT / 64, FEAT / 64), 256>>>(
        Wq, Wk, pM, nullptr, nullptr, FEAT, FEAT, EMB);

    // 1b) u0 = Wk @ bq
    u0_kernel<<<1, 256>>>(Wk, bq, pu0);

    // 2) U = gather(id2feat, nodes) @ M + u0   [10000,256]
    sgemm64<false, true><<<dim3(FEAT / 64, (BATCH + 63) / 64), 256>>>(
        id2feat, pM, pU, pu0, nodes, BATCH, FEAT, FEAT);

    // 3) fused gather + scores + softmax + weighted aggregation
    attn_kernel<<<BATCH, 256>>>(id2feat, neigh, pU, pagg);

    // 4) out = agg @ Wv + bv   [10000,256]
    sgemm64<false, false><<<dim3(EMB / 64, (BATCH + 63) / 64), 256>>>(
        pagg, Wv, out, bv, nullptr, BATCH, EMB, FEAT);
}

// round 2
// speedup vs baseline: 1.1268x; 1.1268x over previous
#include <cuda_runtime.h>

#define FEAT 256
#define EMB  256
#define NSAMP 32
#define BATCH 10000

// Scratch (no device allocation allowed -> __device__ globals)
__device__ float g_M[FEAT * FEAT];     // Wq @ Wk^T
__device__ float g_u0[FEAT];           // Wk @ bq
__device__ float g_U[BATCH * FEAT];    // per-batch score vector in feature space
__device__ float g_agg[BATCH * FEAT];  // attention-weighted neighbor features

// ---------------------------------------------------------------------------
// Small SGEMM (kept for the tiny 256x256x256 M = Wq @ Wk^T)
//   C[M,N] = A[M,K] @ B^T  where B_logical[k][n] = Bp[n*K + k]
// ---------------------------------------------------------------------------
__global__ void sgemm64_tn(const float* __restrict__ A, const float* __restrict__ Bp,
                           float* __restrict__ C, int Mdim, int N, int K)
{
    constexpr int BM = 64, BN = 64, BK = 16;
    __shared__ float As[BK][BM];
    __shared__ float Bs[BK][BN];

    const int tid = threadIdx.x;
    const int tx = tid & 15;
    const int ty = tid >> 4;
    const int m0 = blockIdx.y * BM;
    const int n0 = blockIdx.x * BN;

    const int ar  = tid >> 2;
    const int akq = tid & 3;
    const float4* Arow = (const float4*)(A + (long)(m0 + ar) * K);

    float acc[4][4] = {};

    for (int k0 = 0; k0 < K; k0 += BK) {
        float4 av = Arow[(k0 >> 2) + akq];
        As[akq * 4 + 0][ar] = av.x;
        As[akq * 4 + 1][ar] = av.y;
        As[akq * 4 + 2][ar] = av.z;
        As[akq * 4 + 3][ar] = av.w;

        const int bn  = tid >> 2;
        const int kq2 = tid & 3;
        float4 bv = *(const float4*)&Bp[(long)(n0 + bn) * K + k0 + kq2 * 4];
        Bs[kq2 * 4 + 0][bn] = bv.x;
        Bs[kq2 * 4 + 1][bn] = bv.y;
        Bs[kq2 * 4 + 2][bn] = bv.z;
        Bs[kq2 * 4 + 3][bn] = bv.w;
        __syncthreads();

        #pragma unroll
        for (int k = 0; k < BK; k++) {
            float4 a = *(const float4*)&As[k][ty * 4];
            float4 b = *(const float4*)&Bs[k][tx * 4];
            float av4[4] = {a.x, a.y, a.z, a.w};
            float bv4[4] = {b.x, b.y, b.z, b.w};
            #pragma unroll
            for (int i = 0; i < 4; i++)
                #pragma unroll
                for (int j = 0; j < 4; j++)
                    acc[i][j] += av4[i] * bv4[j];
        }
        __syncthreads();
    }

    #pragma unroll
    for (int i = 0; i < 4; i++) {
        int m = m0 + ty * 4 + i;
        float4 o;
        o.x = acc[i][0]; o.y = acc[i][1]; o.z = acc[i][2]; o.w = acc[i][3];
        *(float4*)&C[(long)m * N + n0 + tx * 4] = o;
    }
}

// ---------------------------------------------------------------------------
// Big SGEMM: C[M,N] = A[M,K] @ B[K,N] (+bias), BM=128 BN=64 BK=16,
// 256 threads, 8x4 microtile, double-buffered smem with register prefetch.
//   HASIDX: A row m gathered through idx[m].
// ---------------------------------------------------------------------------
template <bool HASIDX>
__global__ void __launch_bounds__(256)
sgemm128x64(const float* __restrict__ A, const float* __restrict__ B,
            float* __restrict__ C, const float* __restrict__ bias,
            const int* __restrict__ idx, int Mdim, int N, int K)
{
    constexpr int BM = 128, BN = 64, BK = 16;
    __shared__ float As[2][BK][BM];
    __shared__ float Bs[2][BK][BN];

    const int tid = threadIdx.x;
    const int tx = tid & 15;        // 4 output cols
    const int ty = tid >> 4;        // 8 output rows
    const int m0 = blockIdx.y * BM;
    const int n0 = blockIdx.x * BN;

    // A load mapping: rows r0 = tid>>2 and r0+64, k-quad akq = tid&3
    const int r0  = tid >> 2;
    const int akq = tid & 3;
    int m_a0 = m0 + r0;       if (m_a0 > Mdim - 1) m_a0 = Mdim - 1;
    int m_a1 = m0 + r0 + 64;  if (m_a1 > Mdim - 1) m_a1 = Mdim - 1;
    const long arow0 = HASIDX ? (long)idx[m_a0] : (long)m_a0;
    const long arow1 = HASIDX ? (long)idx[m_a1] : (long)m_a1;
    const float4* A0 = (const float4*)(A + arow0 * (long)K);
    const float4* A1 = (const float4*)(A + arow1 * (long)K);

    // B load mapping: row kr = tid>>4 (0..15), col-quad nq = tid&15
    const int kr = tid >> 4;
    const int nq = tid & 15;

    // ---- prologue: tile 0
    {
        float4 a0 = A0[akq];
        float4 a1 = A1[akq];
        As[0][akq * 4 + 0][r0]      = a0.x;
        As[0][akq * 4 + 1][r0]      = a0.y;
        As[0][akq * 4 + 2][r0]      = a0.z;
        As[0][akq * 4 + 3][r0]      = a0.w;
        As[0][akq * 4 + 0][r0 + 64] = a1.x;
        As[0][akq * 4 + 1][r0 + 64] = a1.y;
        As[0][akq * 4 + 2][r0 + 64] = a1.z;
        As[0][akq * 4 + 3][r0 + 64] = a1.w;
        float4 bv = *(const float4*)&B[(long)kr * N + n0 + nq * 4];
        ((float4*)Bs[0][kr])[nq] = bv;
    }
    __syncthreads();

    float acc[8][4] = {};
    int buf = 0;

    for (int k0 = 0; k0 < K; k0 += BK) {
        const bool has_next = (k0 + BK) < K;
        float4 a0n, a1n, bvn;
        if (has_next) {
            a0n = A0[((k0 + BK) >> 2) + akq];
            a1n = A1[((k0 + BK) >> 2) + akq];
            bvn = *(const float4*)&B[(long)(k0 + BK + kr) * N + n0 + nq * 4];
        }

        #pragma unroll
        for (int k = 0; k < BK; k++) {
            float4 a0 = *(const float4*)&As[buf][k][ty * 8];
            float4 a1 = *(const float4*)&As[buf][k][ty * 8 + 4];
            float4 b  = *(const float4*)&Bs[buf][k][tx * 4];
            float av[8] = {a0.x, a0.y, a0.z, a0.w, a1.x, a1.y, a1.z, a1.w};
            float bv[4] = {b.x, b.y, b.z, b.w};
            #pragma unroll
            for (int i = 0; i < 8; i++)
                #pragma unroll
                for (int j = 0; j < 4; j++)
                    acc[i][j] += av[i] * bv[j];
        }

        if (has_next) {
            const int nb = buf ^ 1;
            As[nb][akq * 4 + 0][r0]      = a0n.x;
            As[nb][akq * 4 + 1][r0]      = a0n.y;
            As[nb][akq * 4 + 2][r0]      = a0n.z;
            As[nb][akq * 4 + 3][r0]      = a0n.w;
            As[nb][akq * 4 + 0][r0 + 64] = a1n.x;
            As[nb][akq * 4 + 1][r0 + 64] = a1n.y;
            As[nb][akq * 4 + 2][r0 + 64] = a1n.z;
            As[nb][akq * 4 + 3][r0 + 64] = a1n.w;
            ((float4*)Bs[nb][kr])[nq] = bvn;
            __syncthreads();
            buf = nb;
        }
    }

    float4 bvec = make_float4(0.f, 0.f, 0.f, 0.f);
    if (bias) bvec = *(const float4*)&bias[n0 + tx * 4];
    #pragma unroll
    for (int i = 0; i < 8; i++) {
        int m = m0 + ty * 8 + i;
        if (m < Mdim) {
            float4 o;
            o.x = acc[i][0] + bvec.x;
            o.y = acc[i][1] + bvec.y;
            o.z = acc[i][2] + bvec.z;
            o.w = acc[i][3] + bvec.w;
            *(float4*)&C[(long)m * N + n0 + tx * 4] = o;
        }
    }
}

// u0[f] = sum_e Wk[f][e] * bq[e]
__global__ void u0_kernel(const float* __restrict__ Wk, const float* __restrict__ bq,
                          float* __restrict__ u0)
{
    __shared__ float sb[EMB];
    const int t = threadIdx.x;
    sb[t] = bq[t];
    __syncthreads();
    float acc = 0.f;
    const float4* row = (const float4*)(Wk + (long)t * EMB);
    #pragma unroll 4
    for (int e4 = 0; e4 < EMB / 4; e4++) {
        float4 w = row[e4];
        acc += w.x * sb[e4 * 4 + 0] + w.y * sb[e4 * 4 + 1] +
               w.z * sb[e4 * 4 + 2] + w.w * sb[e4 * 4 + 3];
    }
    u0[t] = acc;
}

// ---------------------------------------------------------------------------
// Fused attention: one block (256 threads) per batch row.
// Neighbor rows live in REGISTERS (4 per warp, 8 floats/thread/row).
// Only 8KB+8KB of LDS traffic for the cross-warp partial reduction.
// ---------------------------------------------------------------------------
__global__ void __launch_bounds__(256)
attn_kernel(const float* __restrict__ id2feat,
            const int* __restrict__ neigh_idx,
            const float* __restrict__ U,
            float* __restrict__ agg)
{
    __shared__ float spart[8 * FEAT];   // per-warp weighted partials
    __shared__ float sscore[NSAMP];

    const int b = blockIdx.x;
    const int tid  = threadIdx.x;
    const int warp = tid >> 5, lane = tid & 31;

    // Register copy of U row: thread covers float4 slots lane and lane+32,
    // i.e. features [4*lane..4*lane+3] and [128+4*lane..128+4*lane+3].
    const float4* U4 = (const float4*)(U + (long)b * FEAT);
    const float4 uLo = U4[lane];
    const float4 uHi = U4[lane + 32];

    // Gather 4 neighbor rows into registers + dot with U.
    float4 vLo[4], vHi[4];
    const int sbase = warp * 4;
    #pragma unroll
    for (int j = 0; j < 4; j++) {
        const long row = neigh_idx[b * NSAMP + sbase + j];
        const float4* src = (const float4*)(id2feat + row * FEAT);
        vLo[j] = src[lane];
        vHi[j] = src[lane + 32];
        float dot = vLo[j].x * uLo.x + vLo[j].y * uLo.y + vLo[j].z * uLo.z + vLo[j].w * uLo.w
                  + vHi[j].x * uHi.x + vHi[j].y * uHi.y + vHi[j].z * uHi.z + vHi[j].w * uHi.w;
        #pragma unroll
        for (int off = 16; off; off >>= 1)
            dot += __shfl_xor_sync(0xffffffffu, dot, off);
        if (lane == 0) sscore[sbase + j] = dot;
    }
    __syncthreads();

    // Softmax over the 32 neighbor scores (self column is masked out in ref).
    if (warp == 0) {
        float sc = sscore[lane];
        float mx = sc;
        #pragma unroll
        for (int off = 16; off; off >>= 1)
            mx = fmaxf(mx, __shfl_xor_sync(0xffffffffu, mx, off));
        float e = __expf(sc - mx);
        float sum = e;
        #pragma unroll
        for (int off = 16; off; off >>= 1)
            sum += __shfl_xor_sync(0xffffffffu, sum, off);
        sscore[lane] = e / sum;
    }
    __syncthreads();

    // Per-warp weighted partial over its 4 neighbors (registers only).
    float4 pLo = make_float4(0.f, 0.f, 0.f, 0.f);
    float4 pHi = make_float4(0.f, 0.f, 0.f, 0.f);
    #pragma unroll
    for (int j = 0; j < 4; j++) {
        const float w = sscore[sbase + j];
        pLo.x += w * vLo[j].x; pLo.y += w * vLo[j].y;
        pLo.z += w * vLo[j].z; pLo.w += w * vLo[j].w;
        pHi.x += w * vHi[j].x; pHi.y += w * vHi[j].y;
        pHi.z += w * vHi[j].z; pHi.w += w * vHi[j].w;
    }
    float4* sp4 = (float4*)(spart + warp * FEAT);
    sp4[lane]      = pLo;
    sp4[lane + 32] = pHi;
    __syncthreads();

    // Cross-warp reduce: thread tid owns feature tid.
    float acc = 0.f;
    #pragma unroll
    for (int w = 0; w < 8; w++)
        acc += spart[w * FEAT + tid];
    agg[(long)b * FEAT + tid] = acc;
}

extern "C" void kernel_launch(void* const* d_in, const int* in_sizes, int n_in,
                              void* d_out, int out_size)
{
    const int*   nodes   = (const int*)d_in[0];
    const int*   neigh   = (const int*)d_in[1];
    const float* id2feat = (const float*)d_in[2];
    const float* Wq      = (const float*)d_in[3];
    const float* bq      = (const float*)d_in[4];
    const float* Wk      = (const float*)d_in[5];
    // d_in[6] = bk: Q.bk is constant across s -> softmax invariant, unused
    const float* Wv      = (const float*)d_in[7];
    const float* bv      = (const float*)d_in[8];
    float* out = (float*)d_out;

    float *pM, *pu0, *pU, *pagg;
    cudaGetSymbolAddress((void**)&pM,   g_M);
    cudaGetSymbolAddress((void**)&pu0,  g_u0);
    cudaGetSymbolAddress((void**)&pU,   g_U);
    cudaGetSymbolAddress((void**)&pagg, g_agg);

    // 1) M = Wq @ Wk^T  (tiny 256^3)
    sgemm64_tn<<<dim3(FEAT / 64, FEAT / 64), 256>>>(Wq, Wk, pM, FEAT, FEAT, EMB);

    // 1b) u0 = Wk @ bq
    u0_kernel<<<1, 256>>>(Wk, bq, pu0);

    // 2) U = gather(id2feat, nodes) @ M + u0
    sgemm128x64<true><<<dim3(FEAT / 64, (BATCH + 127) / 128), 256>>>(
        id2feat, pM, pU, pu0, nodes, BATCH, FEAT, FEAT);

    // 3) fused gather + scores + softmax + weighted aggregation
    attn_kernel<<<BATCH, 256>>>(id2feat, neigh, pU, pagg);

    // 4) out = agg @ Wv + bv
    sgemm128x64<false><<<dim3(EMB / 64, (BATCH + 127) / 128), 256>>>(
        pagg, Wv, out, bv, nullptr, BATCH, EMB, FEAT);
}

// round 3
// speedup vs baseline: 1.2177x; 1.0807x over previous
#include <cuda_runtime.h>

#define FEAT 256
#define EMB  256
#define NSAMP 32
#define BATCH 10000

// Scratch (no device allocation allowed -> __device__ globals)
__device__ float g_M[FEAT * FEAT];     // Wq @ Wk^T
__device__ float g_u0[FEAT];           // Wk @ bq
__device__ float g_U[BATCH * FEAT];    // per-batch score vector in feature space
__device__ float g_agg[BATCH * FEAT];  // attention-weighted neighbor features

// 64-bit packed-f32 helpers (Blackwell f32x2 pipe: 2 MACs per FFMA2 issue)
__device__ __forceinline__ unsigned long long dup_f32x2(float v) {
    unsigned long long r;
    unsigned u = __float_as_uint(v);
    asm("mov.b64 %0, {%1, %1};" : "=l"(r) : "r"(u));
    return r;
}
__device__ __forceinline__ void fma_f32x2(unsigned long long& acc,
                                          unsigned long long a,
                                          unsigned long long b) {
    asm("fma.rn.f32x2 %0, %1, %2, %0;" : "+l"(acc) : "l"(a), "l"(b));
}
union U64F2 { unsigned long long u; float2 f; };

// ---------------------------------------------------------------------------
// Tiny SGEMM for M = Wq @ Wk^T (256x256x256): 32x32 tiles, 64 blocks.
//   C[m][n] = sum_k A[m][k] * Bp[n][k]
// ---------------------------------------------------------------------------
__global__ void __launch_bounds__(256)
sgemm32_tn(const float* __restrict__ A, const float* __restrict__ Bp,
           float* __restrict__ C, int K)
{
    __shared__ __align__(16) float As[32][32];
    __shared__ __align__(16) float Bs[32][32];

    const int tid = threadIdx.x;
    const int tx = tid & 15;     // 2 cols each
    const int ty = tid >> 4;     // 2 rows each
    const int m0 = blockIdx.y * 32;
    const int n0 = blockIdx.x * 32;

    const int lr = tid >> 3;     // 0..31
    const int kq = tid & 7;      // 0..7 (float4 along k)

    float acc[2][2] = {};

    for (int k0 = 0; k0 < K; k0 += 32) {
        float4 av = *(const float4*)&A[(long)(m0 + lr) * K + k0 + kq * 4];
        As[kq * 4 + 0][lr] = av.x;
        As[kq * 4 + 1][lr] = av.y;
        As[kq * 4 + 2][lr] = av.z;
        As[kq * 4 + 3][lr] = av.w;
        float4 bv = *(const float4*)&Bp[(long)(n0 + lr) * K + k0 + kq * 4];
        Bs[kq * 4 + 0][lr] = bv.x;
        Bs[kq * 4 + 1][lr] = bv.y;
        Bs[kq * 4 + 2][lr] = bv.z;
        Bs[kq * 4 + 3][lr] = bv.w;
        __syncthreads();

        #pragma unroll
        for (int k = 0; k < 32; k++) {
            float a0 = As[k][ty * 2], a1 = As[k][ty * 2 + 1];
            float b0 = Bs[k][tx * 2], b1 = Bs[k][tx * 2 + 1];
            acc[0][0] += a0 * b0; acc[0][1] += a0 * b1;
            acc[1][0] += a1 * b0; acc[1][1] += a1 * b1;
        }
        __syncthreads();
    }

    #pragma unroll
    for (int i = 0; i < 2; i++) {
        float2 o; o.x = acc[i][0]; o.y = acc[i][1];
        *(float2*)&C[(long)(m0 + ty * 2 + i) * 256 + n0 + tx * 2] = o;
    }
}

// ---------------------------------------------------------------------------
// Big SGEMM with packed f32x2 FMA: C[M,N] = A[M,K] @ B[K,N] (+bias)
// BM=128 BN=64 BK=16, 256 threads, 8x4 microtile (4 row-pairs x 4 cols),
// double-buffered smem with register prefetch. HASIDX gathers A rows.
// ---------------------------------------------------------------------------
template <bool HASIDX>
__global__ void __launch_bounds__(256)
sgemm128x64(const float* __restrict__ A, const float* __restrict__ B,
            float* __restrict__ C, const float* __restrict__ bias,
            const int* __restrict__ idx, int Mdim, int N, int K)
{
    constexpr int BM = 128, BN = 64, BK = 16;
    __shared__ __align__(16) float As[2][BK][BM];
    __shared__ __align__(16) float Bs[2][BK][BN];

    const int tid = threadIdx.x;
    const int tx = tid & 15;        // 4 output cols
    const int ty = tid >> 4;        // 8 output rows (4 pairs)
    const int m0 = blockIdx.y * BM;
    const int n0 = blockIdx.x * BN;

    // A load mapping: rows r0 and r0+64, k-quad akq
    const int r0  = tid >> 2;
    const int akq = tid & 3;
    int m_a0 = m0 + r0;       if (m_a0 > Mdim - 1) m_a0 = Mdim - 1;
    int m_a1 = m0 + r0 + 64;  if (m_a1 > Mdim - 1) m_a1 = Mdim - 1;
    const long arow0 = HASIDX ? (long)idx[m_a0] : (long)m_a0;
    const long arow1 = HASIDX ? (long)idx[m_a1] : (long)m_a1;
    const float4* A0 = (const float4*)(A + arow0 * (long)K);
    const float4* A1 = (const float4*)(A + arow1 * (long)K);

    // B load mapping
    const int kr = tid >> 4;
    const int nq = tid & 15;

    // ---- prologue: tile 0
    {
        float4 a0 = A0[akq];
        float4 a1 = A1[akq];
        As[0][akq * 4 + 0][r0]      = a0.x;
        As[0][akq * 4 + 1][r0]      = a0.y;
        As[0][akq * 4 + 2][r0]      = a0.z;
        As[0][akq * 4 + 3][r0]      = a0.w;
        As[0][akq * 4 + 0][r0 + 64] = a1.x;
        As[0][akq * 4 + 1][r0 + 64] = a1.y;
        As[0][akq * 4 + 2][r0 + 64] = a1.z;
        As[0][akq * 4 + 3][r0 + 64] = a1.w;
        float4 bv = *(const float4*)&B[(long)kr * N + n0 + nq * 4];
        ((float4*)Bs[0][kr])[nq] = bv;
    }
    __syncthreads();

    // acc2[i2][j]: packed pair of rows (2*i2, 2*i2+1), column j
    unsigned long long acc2[4][4] = {};
    int buf = 0;

    for (int k0 = 0; k0 < K; k0 += BK) {
        const bool has_next = (k0 + BK) < K;
        float4 a0n, a1n, bvn;
        if (has_next) {
            a0n = A0[((k0 + BK) >> 2) + akq];
            a1n = A1[((k0 + BK) >> 2) + akq];
            bvn = *(const float4*)&B[(long)(k0 + BK + kr) * N + n0 + nq * 4];
        }

        #pragma unroll
        for (int k = 0; k < BK; k++) {
            // A row-pairs come straight out of LDS.128 as 64-bit packs
            ulonglong2 aA = *(const ulonglong2*)&As[buf][k][ty * 8];
            ulonglong2 aB = *(const ulonglong2*)&As[buf][k][ty * 8 + 4];
            unsigned long long a2[4] = {aA.x, aA.y, aB.x, aB.y};
            float4 b = *(const float4*)&Bs[buf][k][tx * 4];
            unsigned long long bd[4] = {dup_f32x2(b.x), dup_f32x2(b.y),
                                        dup_f32x2(b.z), dup_f32x2(b.w)};
            #pragma unroll
            for (int i2 = 0; i2 < 4; i2++)
                #pragma unroll
                for (int j = 0; j < 4; j++)
                    fma_f32x2(acc2[i2][j], a2[i2], bd[j]);
        }

        if (has_next) {
            const int nb = buf ^ 1;
            As[nb][akq * 4 + 0][r0]      = a0n.x;
            As[nb][akq * 4 + 1][r0]      = a0n.y;
            As[nb][akq * 4 + 2][r0]      = a0n.z;
            As[nb][akq * 4 + 3][r0]      = a0n.w;
            As[nb][akq * 4 + 0][r0 + 64] = a1n.x;
            As[nb][akq * 4 + 1][r0 + 64] = a1n.y;
            As[nb][akq * 4 + 2][r0 + 64] = a1n.z;
            As[nb][akq * 4 + 3][r0 + 64] = a1n.w;
            ((float4*)Bs[nb][kr])[nq] = bvn;
            __syncthreads();
            buf = nb;
        }
    }

    float4 bvec = make_float4(0.f, 0.f, 0.f, 0.f);
    if (bias) bvec = *(const float4*)&bias[n0 + tx * 4];

    #pragma unroll
    for (int i2 = 0; i2 < 4; i2++) {
        U64F2 c0, c1, c2, c3;
        c0.u = acc2[i2][0]; c1.u = acc2[i2][1];
        c2.u = acc2[i2][2]; c3.u = acc2[i2][3];
        int mLo = m0 + ty * 8 + 2 * i2;
        int mHi = mLo + 1;
        if (mLo < Mdim) {
            float4 o;
            o.x = c0.f.x + bvec.x; o.y = c1.f.x + bvec.y;
            o.z = c2.f.x + bvec.z; o.w = c3.f.x + bvec.w;
            *(float4*)&C[(long)mLo * N + n0 + tx * 4] = o;
        }
        if (mHi < Mdim) {
            float4 o;
            o.x = c0.f.y + bvec.x; o.y = c1.f.y + bvec.y;
            o.z = c2.f.y + bvec.z; o.w = c3.f.y + bvec.w;
            *(float4*)&C[(long)mHi * N + n0 + tx * 4] = o;
        }
    }
}

// u0[f] = sum_e Wk[f][e] * bq[e]
__global__ void u0_kernel(const float* __restrict__ Wk, const float* __restrict__ bq,
                          float* __restrict__ u0)
{
    __shared__ float sb[EMB];
    const int t = threadIdx.x;
    sb[t] = bq[t];
    __syncthreads();
    float acc = 0.f;
    const float4* row = (const float4*)(Wk + (long)t * EMB);
    #pragma unroll 4
    for (int e4 = 0; e4 < EMB / 4; e4++) {
        float4 w = row[e4];
        acc += w.x * sb[e4 * 4 + 0] + w.y * sb[e4 * 4 + 1] +
               w.z * sb[e4 * 4 + 2] + w.w * sb[e4 * 4 + 3];
    }
    u0[t] = acc;
}

// ---------------------------------------------------------------------------
// Fused attention: one block (256 threads) per batch row.
// Neighbor rows live in REGISTERS (4 per warp, 8 floats/thread/row).
// ---------------------------------------------------------------------------
__global__ void __launch_bounds__(256)
attn_kernel(const float* __restrict__ id2feat,
            const int* __restrict__ neigh_idx,
            const float* __restrict__ U,
            float* __restrict__ agg)
{
    __shared__ float spart[8 * FEAT];   // per-warp weighted partials
    __shared__ float sscore[NSAMP];

    const int b = blockIdx.x;
    const int tid  = threadIdx.x;
    const int warp = tid >> 5, lane = tid & 31;

    const float4* U4 = (const float4*)(U + (long)b * FEAT);
    const float4 uLo = U4[lane];
    const float4 uHi = U4[lane + 32];

    float4 vLo[4], vHi[4];
    const int sbase = warp * 4;
    #pragma unroll
    for (int j = 0; j < 4; j++) {
        const long row = neigh_idx[b * NSAMP + sbase + j];
        const float4* src = (const float4*)(id2feat + row * FEAT);
        vLo[j] = src[lane];
        vHi[j] = src[lane + 32];
        float dot = vLo[j].x * uLo.x + vLo[j].y * uLo.y + vLo[j].z * uLo.z + vLo[j].w * uLo.w
                  + vHi[j].x * uHi.x + vHi[j].y * uHi.y + vHi[j].z * uHi.z + vHi[j].w * uHi.w;
        #pragma unroll
        for (int off = 16; off; off >>= 1)
            dot += __shfl_xor_sync(0xffffffffu, dot, off);
        if (lane == 0) sscore[sbase + j] = dot;
    }
    __syncthreads();

    if (warp == 0) {
        float sc = sscore[lane];
        float mx = sc;
        #pragma unroll
        for (int off = 16; off; off >>= 1)
            mx = fmaxf(mx, __shfl_xor_sync(0xffffffffu, mx, off));
        float e = __expf(sc - mx);
        float sum = e;
        #pragma unroll
        for (int off = 16; off; off >>= 1)
            sum += __shfl_xor_sync(0xffffffffu, sum, off);
        sscore[lane] = e / sum;
    }
    __syncthreads();

    float4 pLo = make_float4(0.f, 0.f, 0.f, 0.f);
    float4 pHi = make_float4(0.f, 0.f, 0.f, 0.f);
    #pragma unroll
    for (int j = 0; j < 4; j++) {
        const float w = sscore[sbase + j];
        pLo.x += w * vLo[j].x; pLo.y += w * vLo[j].y;
        pLo.z += w * vLo[j].z; pLo.w += w * vLo[j].w;
        pHi.x += w * vHi[j].x; pHi.y += w * vHi[j].y;
        pHi.z += w * vHi[j].z; pHi.w += w * vHi[j].w;
    }
    float4* sp4 = (float4*)(spart + warp * FEAT);
    sp4[lane]      = pLo;
    sp4[lane + 32] = pHi;
    __syncthreads();

    float acc = 0.f;
    #pragma unroll
    for (int w = 0; w < 8; w++)
        acc += spart[w * FEAT + tid];
    agg[(long)b * FEAT + tid] = acc;
}

extern "C" void kernel_launch(void* const* d_in, const int* in_sizes, int n_in,
                              void* d_out, int out_size)
{
    const int*   nodes   = (const int*)d_in[0];
    const int*   neigh   = (const int*)d_in[1];
    const float* id2feat = (const float*)d_in[2];
    const float* Wq      = (const float*)d_in[3];
    const float* bq      = (const float*)d_in[4];
    const float* Wk      = (const float*)d_in[5];
    // d_in[6] = bk: Q.bk is constant across s -> softmax invariant, unused
    const float* Wv      = (const float*)d_in[7];
    const float* bv      = (const float*)d_in[8];
    float* out = (float*)d_out;

    float *pM, *pu0, *pU, *pagg;
    cudaGetSymbolAddress((void**)&pM,   g_M);
    cudaGetSymbolAddress((void**)&pu0,  g_u0);
    cudaGetSymbolAddress((void**)&pU,   g_U);
    cudaGetSymbolAddress((void**)&pagg, g_agg);

    // 1) M = Wq @ Wk^T  (tiny 256^3, 64 blocks)
    sgemm32_tn<<<dim3(FEAT / 32, FEAT / 32), 256>>>(Wq, Wk, pM, EMB);

    // 1b) u0 = Wk @ bq
    u0_kernel<<<1, 256>>>(Wk, bq, pu0);

    // 2) U = gather(id2feat, nodes) @ M + u0
    sgemm128x64<true><<<dim3(FEAT / 64, (BATCH + 127) / 128), 256>>>(
        id2feat, pM, pU, pu0, nodes, BATCH, FEAT, FEAT);

    // 3) fused gather + scores + softmax + weighted aggregation
    attn_kernel<<<BATCH, 256>>>(id2feat, neigh, pU, pagg);

    // 4) out = agg @ Wv + bv
    sgemm128x64<false><<<dim3(EMB / 64, (BATCH + 127) / 128), 256>>>(
        pagg, Wv, out, bv, nullptr, BATCH, EMB, FEAT);
}

// round 9
// speedup vs baseline: 1.2316x; 1.0113x over previous
#include <cuda_runtime.h>

#define FEAT 256
#define EMB  256
#define NSAMP 32
#define BATCH 10000

// Scratch (no device allocation allowed -> __device__ globals)
__device__ float g_M[FEAT * FEAT];     // Wq @ Wk^T
__device__ float g_u0[FEAT];           // Wk @ bq
__device__ float g_U[BATCH * FEAT];    // per-batch score vector in feature space
__device__ float g_agg[BATCH * FEAT];  // attention-weighted neighbor features

// 64-bit packed-f32 helpers (Blackwell f32x2 pipe: 2 MACs per FFMA2 issue)
__device__ __forceinline__ unsigned long long dup_f32x2(float v) {
    unsigned long long r;
    unsigned u = __float_as_uint(v);
    asm("mov.b64 %0, {%1, %1};" : "=l"(r) : "r"(u));
    return r;
}
__device__ __forceinline__ void fma_f32x2(unsigned long long& acc,
                                          unsigned long long a,
                                          unsigned long long b) {
    asm("fma.rn.f32x2 %0, %1, %2, %0;" : "+l"(acc) : "l"(a), "l"(b));
}
union U64F2 { unsigned long long u; float2 f; };

// ---------------------------------------------------------------------------
// Tiny SGEMM for M = Wq @ Wk^T (256x256x256): 32x32 tiles, 64 blocks.
// ---------------------------------------------------------------------------
__global__ void __launch_bounds__(256)
sgemm32_tn(const float* __restrict__ A, const float* __restrict__ Bp,
           float* __restrict__ C, int K)
{
    __shared__ __align__(16) float As[32][32];
    __shared__ __align__(16) float Bs[32][32];

    const int tid = threadIdx.x;
    const int tx = tid & 15;     // 2 cols each
    const int ty = tid >> 4;     // 2 rows each
    const int m0 = blockIdx.y * 32;
    const int n0 = blockIdx.x * 32;

    const int lr = tid >> 3;     // 0..31
    const int kq = tid & 7;      // 0..7 (float4 along k)

    float acc[2][2] = {};

    for (int k0 = 0; k0 < K; k0 += 32) {
        float4 av = *(const float4*)&A[(long)(m0 + lr) * K + k0 + kq * 4];
        As[kq * 4 + 0][lr] = av.x;
        As[kq * 4 + 1][lr] = av.y;
        As[kq * 4 + 2][lr] = av.z;
        As[kq * 4 + 3][lr] = av.w;
        float4 bv = *(const float4*)&Bp[(long)(n0 + lr) * K + k0 + kq * 4];
        Bs[kq * 4 + 0][lr] = bv.x;
        Bs[kq * 4 + 1][lr] = bv.y;
        Bs[kq * 4 + 2][lr] = bv.z;
        Bs[kq * 4 + 3][lr] = bv.w;
        __syncthreads();

        #pragma unroll
        for (int k = 0; k < 32; k++) {
            float a0 = As[k][ty * 2], a1 = As[k][ty * 2 + 1];
            float b0 = Bs[k][tx * 2], b1 = Bs[k][tx * 2 + 1];
            acc[0][0] += a0 * b0; acc[0][1] += a0 * b1;
            acc[1][0] += a1 * b0; acc[1][1] += a1 * b1;
        }
        __syncthreads();
    }

    #pragma unroll
    for (int i = 0; i < 2; i++) {
        float2 o; o.x = acc[i][0]; o.y = acc[i][1];
        *(float2*)&C[(long)(m0 + ty * 2 + i) * 256 + n0 + tx * 2] = o;
    }
}

// ---------------------------------------------------------------------------
// Big SGEMM with packed f32x2 FMA: C[M,N] = A[M,K] @ B[K,N] (+bias)
// BM=128 BN=64 BK=16, 256 threads, 8x4 microtile (4 row-pairs x 4 cols),
// double-buffered smem with register prefetch. HASIDX gathers A rows.
// (verified at 159.7us in R3 — unchanged)
// ---------------------------------------------------------------------------
template <bool HASIDX>
__global__ void __launch_bounds__(256)
sgemm128x64(const float* __restrict__ A, const float* __restrict__ B,
            float* __restrict__ C, const float* __restrict__ bias,
            const int* __restrict__ idx, int Mdim, int N, int K)
{
    constexpr int BM = 128, BN = 64, BK = 16;
    __shared__ __align__(16) float As[2][BK][BM];
    __shared__ __align__(16) float Bs[2][BK][BN];

    const int tid = threadIdx.x;
    const int tx = tid & 15;        // 4 output cols
    const int ty = tid >> 4;        // 8 output rows (4 pairs)
    const int m0 = blockIdx.y * BM;
    const int n0 = blockIdx.x * BN;

    // A load mapping: rows r0 and r0+64, k-quad akq
    const int r0  = tid >> 2;
    const int akq = tid & 3;
    int m_a0 = m0 + r0;       if (m_a0 > Mdim - 1) m_a0 = Mdim - 1;
    int m_a1 = m0 + r0 + 64;  if (m_a1 > Mdim - 1) m_a1 = Mdim - 1;
    const long arow0 = HASIDX ? (long)idx[m_a0] : (long)m_a0;
    const long arow1 = HASIDX ? (long)idx[m_a1] : (long)m_a1;
    const float4* A0 = (const float4*)(A + arow0 * (long)K);
    const float4* A1 = (const float4*)(A + arow1 * (long)K);

    // B load mapping
    const int kr = tid >> 4;
    const int nq = tid & 15;

    // ---- prologue: tile 0
    {
        float4 a0 = A0[akq];
        float4 a1 = A1[akq];
        As[0][akq * 4 + 0][r0]      = a0.x;
        As[0][akq * 4 + 1][r0]      = a0.y;
        As[0][akq * 4 + 2][r0]      = a0.z;
        As[0][akq * 4 + 3][r0]      = a0.w;
        As[0][akq * 4 + 0][r0 + 64] = a1.x;
        As[0][akq * 4 + 1][r0 + 64] = a1.y;
        As[0][akq * 4 + 2][r0 + 64] = a1.z;
        As[0][akq * 4 + 3][r0 + 64] = a1.w;
        float4 bv = *(const float4*)&B[(long)kr * N + n0 + nq * 4];
        ((float4*)Bs[0][kr])[nq] = bv;
    }
    __syncthreads();

    // acc2[i2][j]: packed pair of rows (2*i2, 2*i2+1), column j
    unsigned long long acc2[4][4] = {};
    int buf = 0;

    for (int k0 = 0; k0 < K; k0 += BK) {
        const bool has_next = (k0 + BK) < K;
        float4 a0n, a1n, bvn;
        if (has_next) {
            a0n = A0[((k0 + BK) >> 2) + akq];
            a1n = A1[((k0 + BK) >> 2) + akq];
            bvn = *(const float4*)&B[(long)(k0 + BK + kr) * N + n0 + nq * 4];
        }

        #pragma unroll
        for (int k = 0; k < BK; k++) {
            // A row-pairs come straight out of LDS.128 as 64-bit packs
            ulonglong2 aA = *(const ulonglong2*)&As[buf][k][ty * 8];
            ulonglong2 aB = *(const ulonglong2*)&As[buf][k][ty * 8 + 4];
            unsigned long long a2[4] = {aA.x, aA.y, aB.x, aB.y};
            float4 b = *(const float4*)&Bs[buf][k][tx * 4];
            unsigned long long bd[4] = {dup_f32x2(b.x), dup_f32x2(b.y),
                                        dup_f32x2(b.z), dup_f32x2(b.w)};
            #pragma unroll
            for (int i2 = 0; i2 < 4; i2++)
                #pragma unroll
                for (int j = 0; j < 4; j++)
                    fma_f32x2(acc2[i2][j], a2[i2], bd[j]);
        }

        if (has_next) {
            const int nb = buf ^ 1;
            As[nb][akq * 4 + 0][r0]      = a0n.x;
            As[nb][akq * 4 + 1][r0]      = a0n.y;
            As[nb][akq * 4 + 2][r0]      = a0n.z;
            As[nb][akq * 4 + 3][r0]      = a0n.w;
            As[nb][akq * 4 + 0][r0 + 64] = a1n.x;
            As[nb][akq * 4 + 1][r0 + 64] = a1n.y;
            As[nb][akq * 4 + 2][r0 + 64] = a1n.z;
            As[nb][akq * 4 + 3][r0 + 64] = a1n.w;
            ((float4*)Bs[nb][kr])[nq] = bvn;
            __syncthreads();
            buf = nb;
        }
    }

    float4 bvec = make_float4(0.f, 0.f, 0.f, 0.f);
    if (bias) bvec = *(const float4*)&bias[n0 + tx * 4];

    #pragma unroll
    for (int i2 = 0; i2 < 4; i2++) {
        U64F2 c0, c1, c2, c3;
        c0.u = acc2[i2][0]; c1.u = acc2[i2][1];
        c2.u = acc2[i2][2]; c3.u = acc2[i2][3];
        int mLo = m0 + ty * 8 + 2 * i2;
        int mHi = mLo + 1;
        if (mLo < Mdim) {
            float4 o;
            o.x = c0.f.x + bvec.x; o.y = c1.f.x + bvec.y;
            o.z = c2.f.x + bvec.z; o.w = c3.f.x + bvec.w;
            *(float4*)&C[(long)mLo * N + n0 + tx * 4] = o;
        }
        if (mHi < Mdim) {
            float4 o;
            o.x = c0.f.y + bvec.x; o.y = c1.f.y + bvec.y;
            o.z = c2.f.y + bvec.z; o.w = c3.f.y + bvec.w;
            *(float4*)&C[(long)mHi * N + n0 + tx * 4] = o;
        }
    }
}

// u0[f] = sum_e Wk[f][e] * bq[e]
__global__ void u0_kernel(const float* __restrict__ Wk, const float* __restrict__ bq,
                          float* __restrict__ u0)
{
    __shared__ float sb[EMB];
    const int t = threadIdx.x;
    sb[t] = bq[t];
    __syncthreads();
    float acc = 0.f;
    const float4* row = (const float4*)(Wk + (long)t * EMB);
    #pragma unroll 4
    for (int e4 = 0; e4 < EMB / 4; e4++) {
        float4 w = row[e4];
        acc += w.x * sb[e4 * 4 + 0] + w.y * sb[e4 * 4 + 1] +
               w.z * sb[e4 * 4 + 2] + w.w * sb[e4 * 4 + 3];
    }
    u0[t] = acc;
}

// ---------------------------------------------------------------------------
// Fused attention: one block (256 threads) per batch row; rows in registers.
// NEW: all 8 gather LDG.128s + 2 U-loads front-batched (MLP~10) before any
// dependent FMA; warp's 4 neighbor indices fetched as one int4.
// ---------------------------------------------------------------------------
__global__ void __launch_bounds__(256)
attn_kernel(const float* __restrict__ id2feat,
            const int* __restrict__ neigh_idx,
            const float* __restrict__ U,
            float* __restrict__ agg)
{
    __shared__ float spart[8 * FEAT];
    __shared__ float sscore[NSAMP];

    const int b = blockIdx.x;
    const int tid = threadIdx.x;
    const int warp = tid >> 5, lane = tid & 31;

    // 4 neighbor indices for this warp in one 16B load (uniform across lanes)
    const int4 nidx = ((const int4*)(neigh_idx + b * NSAMP))[warp];
    const float4* src0 = (const float4*)(id2feat + (long)nidx.x * FEAT);
    const float4* src1 = (const float4*)(id2feat + (long)nidx.y * FEAT);
    const float4* src2 = (const float4*)(id2feat + (long)nidx.z * FEAT);
    const float4* src3 = (const float4*)(id2feat + (long)nidx.w * FEAT);
    const float4* U4 = (const float4*)(U + (long)b * FEAT);

    // front-batch ALL loads before any dependent math
    float4 vLo[4], vHi[4];
    vLo[0] = src0[lane];      vLo[1] = src1[lane];
    vLo[2] = src2[lane];      vLo[3] = src3[lane];
    vHi[0] = src0[lane + 32]; vHi[1] = src1[lane + 32];
    vHi[2] = src2[lane + 32]; vHi[3] = src3[lane + 32];
    const float4 uLo = U4[lane];
    const float4 uHi = U4[lane + 32];

    const int sbase = warp * 4;
    #pragma unroll
    for (int j = 0; j < 4; j++) {
        float dot = vLo[j].x * uLo.x + vLo[j].y * uLo.y + vLo[j].z * uLo.z + vLo[j].w * uLo.w
                  + vHi[j].x * uHi.x + vHi[j].y * uHi.y + vHi[j].z * uHi.z + vHi[j].w * uHi.w;
        #pragma unroll
        for (int off = 16; off; off >>= 1)
            dot += __shfl_xor_sync(0xffffffffu, dot, off);
        if (lane == 0) sscore[sbase + j] = dot;
    }
    __syncthreads();

    // Softmax over the 32 neighbor scores (self column masked in reference)
    if (warp == 0) {
        float sc = sscore[lane];
        float mx = sc;
        #pragma unroll
        for (int off = 16; off; off >>= 1)
            mx = fmaxf(mx, __shfl_xor_sync(0xffffffffu, mx, off));
        float e = __expf(sc - mx);
        float sum = e;
        #pragma unroll
        for (int off = 16; off; off >>= 1)
            sum += __shfl_xor_sync(0xffffffffu, sum, off);
        sscore[lane] = e / sum;
    }
    __syncthreads();

    float4 pLo = make_float4(0.f, 0.f, 0.f, 0.f);
    float4 pHi = make_float4(0.f, 0.f, 0.f, 0.f);
    #pragma unroll
    for (int j = 0; j < 4; j++) {
        const float w = sscore[sbase + j];
        pLo.x += w * vLo[j].x; pLo.y += w * vLo[j].y;
        pLo.z += w * vLo[j].z; pLo.w += w * vLo[j].w;
        pHi.x += w * vHi[j].x; pHi.y += w * vHi[j].y;
        pHi.z += w * vHi[j].z; pHi.w += w * vHi[j].w;
    }
    float4* sp4 = (float4*)(spart + warp * FEAT);
    sp4[lane]      = pLo;
    sp4[lane + 32] = pHi;
    __syncthreads();

    float acc = 0.f;
    #pragma unroll
    for (int w = 0; w < 8; w++)
        acc += spart[w * FEAT + tid];
    agg[(long)b * FEAT + tid] = acc;
}

extern "C" void kernel_launch(void* const* d_in, const int* in_sizes, int n_in,
                              void* d_out, int out_size)
{
    const int*   nodes   = (const int*)d_in[0];
    const int*   neigh   = (const int*)d_in[1];
    const float* id2feat = (const float*)d_in[2];
    const float* Wq      = (const float*)d_in[3];
    const float* bq      = (const float*)d_in[4];
    const float* Wk      = (const float*)d_in[5];
    // d_in[6] = bk: Q.bk is constant across s -> softmax invariant, unused
    const float* Wv      = (const float*)d_in[7];
    const float* bv      = (const float*)d_in[8];
    float* out = (float*)d_out;

    float *pM, *pu0, *pU, *pagg;
    cudaGetSymbolAddress((void**)&pM,   g_M);
    cudaGetSymbolAddress((void**)&pu0,  g_u0);
    cudaGetSymbolAddress((void**)&pU,   g_U);
    cudaGetSymbolAddress((void**)&pagg, g_agg);

    // 1) M = Wq @ Wk^T  (tiny 256^3, 64 blocks)
    sgemm32_tn<<<dim3(FEAT / 32, FEAT / 32), 256>>>(Wq, Wk, pM, EMB);

    // 1b) u0 = Wk @ bq
    u0_kernel<<<1, 256>>>(Wk, bq, pu0);

    // 2) U = gather(id2feat, nodes) @ M + u0
    sgemm128x64<true><<<dim3(FEAT / 64, (BATCH + 127) / 128), 256>>>(
        id2feat, pM, pU, pu0, nodes, BATCH, FEAT, FEAT);

    // 3) fused gather + scores + softmax + weighted aggregation
    attn_kernel<<<BATCH, 256>>>(id2feat, neigh, pU, pagg);

    // 4) out = agg @ Wv + bv
    sgemm128x64<false><<<dim3(EMB / 64, (BATCH + 127) / 128), 256>>>(
        pagg, Wv, out, bv, nullptr, BATCH, EMB, FEAT);
}